// round 7
// baseline (speedup 1.0000x reference)
#include <cuda_runtime.h>
#include <math_constants.h>
#include <mma.h>
#include <cstdint>

using namespace nvcuda;

constexpr int Bn = 4, Tn = 4096, Dn = 1024, Hn = 64;
constexpr int Mt = Bn * Tn;              // 16384 tokens
constexpr float SCALE = 0.125f;          // 1/sqrt(64)

// ----------------------------- scratch --------------------------------------
__device__ float g_Q[(size_t)Mt * Hn];           // Q (near-fp32, 3xTF32 product)
__device__ float g_K[(size_t)Mt * Hn];           // K
__device__ float g_V[(size_t)Mt * Dn];           // V, natural [token][e]
__device__ float g_S[(size_t)Bn * Tn * Tn];      // raw scores -> normalized P

// ----------------------------- wmma types -----------------------------------
using FragA  = wmma::fragment<wmma::matrix_a, 16, 16, 8, wmma::precision::tf32, wmma::row_major>;
using FragBc = wmma::fragment<wmma::matrix_b, 16, 16, 8, wmma::precision::tf32, wmma::col_major>;
using FragBr = wmma::fragment<wmma::matrix_b, 16, 16, 8, wmma::precision::tf32, wmma::row_major>;
using FragC  = wmma::fragment<wmma::accumulator, 16, 16, 8, float>;

template <class F>
__device__ __forceinline__ void split_frag(const F& x, F& hi, F& lo) {
#pragma unroll
    for (int i = 0; i < x.num_elements; ++i) {
        float h = wmma::__float_to_tf32(x.x[i]);
        hi.x[i] = h;
        lo.x[i] = wmma::__float_to_tf32(x.x[i] - h);
    }
}

// =============================================================================
// Kernel 1: fused Q+K projection, 3xTF32. C[128 x 128] = x_tile * [Wq;Wk]^T
// =============================================================================
__global__ __launch_bounds__(256) void proj_qk(const float* __restrict__ x,
                                               const float* __restrict__ Wq,
                                               const float* __restrict__ Wk) {
    __shared__ float As[128][36];
    __shared__ float Bs[128][36];
    const int tid = threadIdx.x, wid = tid >> 5;
    const int bm = blockIdx.x * 128;
    const int wm = (wid >> 2) * 64, wn = (wid & 3) * 32;

    FragC acc[4][2];
#pragma unroll
    for (int i = 0; i < 4; ++i)
#pragma unroll
        for (int j = 0; j < 2; ++j) wmma::fill_fragment(acc[i][j], 0.0f);

    for (int k0 = 0; k0 < Dn; k0 += 32) {
#pragma unroll
        for (int t = 0; t < 4; ++t) {
            const int idx = tid + t * 256, r = idx >> 3, c = (idx & 7) * 4;
            float4 v = *(const float4*)(x + (size_t)(bm + r) * Dn + k0 + c);
            As[r][c] = v.x; As[r][c + 1] = v.y; As[r][c + 2] = v.z; As[r][c + 3] = v.w;
            const float* wsrc = (r < 64) ? (Wq + (size_t)r * Dn) : (Wk + (size_t)(r - 64) * Dn);
            float4 w = *(const float4*)(wsrc + k0 + c);
            Bs[r][c] = w.x; Bs[r][c + 1] = w.y; Bs[r][c + 2] = w.z; Bs[r][c + 3] = w.w;
        }
        __syncthreads();
#pragma unroll
        for (int kk = 0; kk < 4; ++kk) {
            FragA ah[4], al[4];
            FragBc bh[2], bl[2];
#pragma unroll
            for (int i = 0; i < 4; ++i) {
                FragA a;
                wmma::load_matrix_sync(a, &As[wm + i * 16][kk * 8], 36);
                split_frag(a, ah[i], al[i]);
            }
#pragma unroll
            for (int j = 0; j < 2; ++j) {
                FragBc b;
                wmma::load_matrix_sync(b, &Bs[wn + j * 16][kk * 8], 36);
                split_frag(b, bh[j], bl[j]);
            }
#pragma unroll
            for (int i = 0; i < 4; ++i)
#pragma unroll
                for (int j = 0; j < 2; ++j) {
                    wmma::mma_sync(acc[i][j], ah[i], bh[j], acc[i][j]);
                    wmma::mma_sync(acc[i][j], ah[i], bl[j], acc[i][j]);
                    wmma::mma_sync(acc[i][j], al[i], bh[j], acc[i][j]);
                }
        }
        __syncthreads();
    }
#pragma unroll
    for (int i = 0; i < 4; ++i)
#pragma unroll
        for (int j = 0; j < 2; ++j) {
            const int row = bm + wm + i * 16;
            const int col = wn + j * 16;
            float* dst = (col < 64) ? (g_Q + (size_t)row * Hn + col)
                                    : (g_K + (size_t)row * Hn + (col - 64));
            wmma::store_matrix_sync(dst, acc[i][j], Hn, wmma::mem_row_major);
        }
}

// =============================================================================
// Kernel 2: V projection, plain tf32. Grid: x = e-tile (fast, shares x row-tile
// via L2), y = token row-tile.
// =============================================================================
__global__ __launch_bounds__(256) void proj_v(const float* __restrict__ x,
                                              const float* __restrict__ Wv) {
    __shared__ float As[128][36];
    __shared__ float Bs[128][36];
    const int tid = threadIdx.x, wid = tid >> 5;
    const int e0 = blockIdx.x * 128;
    const int bm = blockIdx.y * 128;
    const int wm = (wid >> 2) * 64, wn = (wid & 3) * 32;

    FragC acc[4][2];
#pragma unroll
    for (int i = 0; i < 4; ++i)
#pragma unroll
        for (int j = 0; j < 2; ++j) wmma::fill_fragment(acc[i][j], 0.0f);

    for (int k0 = 0; k0 < Dn; k0 += 32) {
#pragma unroll
        for (int t = 0; t < 4; ++t) {
            const int idx = tid + t * 256, r = idx >> 3, c = (idx & 7) * 4;
            float4 v = *(const float4*)(x + (size_t)(bm + r) * Dn + k0 + c);
            As[r][c] = wmma::__float_to_tf32(v.x);
            As[r][c + 1] = wmma::__float_to_tf32(v.y);
            As[r][c + 2] = wmma::__float_to_tf32(v.z);
            As[r][c + 3] = wmma::__float_to_tf32(v.w);
            float4 w = *(const float4*)(Wv + (size_t)(e0 + r) * Dn + k0 + c);
            Bs[r][c] = wmma::__float_to_tf32(w.x);
            Bs[r][c + 1] = wmma::__float_to_tf32(w.y);
            Bs[r][c + 2] = wmma::__float_to_tf32(w.z);
            Bs[r][c + 3] = wmma::__float_to_tf32(w.w);
        }
        __syncthreads();
#pragma unroll
        for (int kk = 0; kk < 4; ++kk) {
            FragA a[4];
            FragBc b[2];
#pragma unroll
            for (int i = 0; i < 4; ++i)
                wmma::load_matrix_sync(a[i], &As[wm + i * 16][kk * 8], 36);
#pragma unroll
            for (int j = 0; j < 2; ++j)
                wmma::load_matrix_sync(b[j], &Bs[wn + j * 16][kk * 8], 36);
#pragma unroll
            for (int i = 0; i < 4; ++i)
#pragma unroll
                for (int j = 0; j < 2; ++j)
                    wmma::mma_sync(acc[i][j], a[i], b[j], acc[i][j]);
        }
        __syncthreads();
    }
#pragma unroll
    for (int i = 0; i < 4; ++i)
#pragma unroll
        for (int j = 0; j < 2; ++j)
            wmma::store_matrix_sync(g_V + (size_t)(bm + wm + i * 16) * Dn + e0 + wn + j * 16,
                                    acc[i][j], Dn, wmma::mem_row_major);
}

// =============================================================================
// Kernel 3: scores, 3xTF32, SCALE folded into Q. One CTA per (rt, jt<=rt, b).
// =============================================================================
__global__ __launch_bounds__(256) void scores_k() {
    extern __shared__ float dynf[];
    float (*Qs)[68] = (float(*)[68])dynf;               // 128 x 68
    float (*Ks)[68] = (float(*)[68])(dynf + 128 * 68);  // 128 x 68

    const int tid = threadIdx.x, wid = tid >> 5;
    const int b = blockIdx.y;
    int idx = blockIdx.x;
    int rt = (int)((sqrtf(8.0f * idx + 1.0f) - 1.0f) * 0.5f);
    while ((rt + 1) * (rt + 2) / 2 <= idx) ++rt;
    while (rt * (rt + 1) / 2 > idx) --rt;
    const int jt = idx - rt * (rt + 1) / 2;
    const int i0 = rt * 128, j0 = jt * 128;
    const int wm = (wid >> 2) * 64, wn = (wid & 3) * 32;

    const float* Qb = g_Q + (size_t)(b * Tn + i0) * Hn;
    const float* Kb = g_K + (size_t)(b * Tn + j0) * Hn;
    float* Sb = g_S + (size_t)b * Tn * Tn;

#pragma unroll
    for (int t = 0; t < 8; ++t) {
        const int id2 = tid + t * 256, r = id2 >> 4, c = (id2 & 15) * 4;
        float4 q = *(const float4*)(Qb + (size_t)r * Hn + c);
        Qs[r][c] = q.x * SCALE; Qs[r][c + 1] = q.y * SCALE;
        Qs[r][c + 2] = q.z * SCALE; Qs[r][c + 3] = q.w * SCALE;
        float4 k = *(const float4*)(Kb + (size_t)r * Hn + c);
        Ks[r][c] = k.x; Ks[r][c + 1] = k.y; Ks[r][c + 2] = k.z; Ks[r][c + 3] = k.w;
    }
    __syncthreads();

    FragC acc[4][2];
#pragma unroll
    for (int i = 0; i < 4; ++i)
#pragma unroll
        for (int j = 0; j < 2; ++j) wmma::fill_fragment(acc[i][j], 0.0f);

#pragma unroll
    for (int kk = 0; kk < 8; ++kk) {
        FragA ah[4], al[4];
        FragBc bh[2], bl[2];
#pragma unroll
        for (int i = 0; i < 4; ++i) {
            FragA a;
            wmma::load_matrix_sync(a, &Qs[wm + i * 16][kk * 8], 68);
            split_frag(a, ah[i], al[i]);
        }
#pragma unroll
        for (int j = 0; j < 2; ++j) {
            FragBc bb;
            wmma::load_matrix_sync(bb, &Ks[wn + j * 16][kk * 8], 68);
            split_frag(bb, bh[j], bl[j]);
        }
#pragma unroll
        for (int i = 0; i < 4; ++i)
#pragma unroll
            for (int j = 0; j < 2; ++j) {
                wmma::mma_sync(acc[i][j], ah[i], bh[j], acc[i][j]);
                wmma::mma_sync(acc[i][j], ah[i], bl[j], acc[i][j]);
                wmma::mma_sync(acc[i][j], al[i], bh[j], acc[i][j]);
            }
    }
#pragma unroll
    for (int i = 0; i < 4; ++i)
#pragma unroll
        for (int j = 0; j < 2; ++j)
            wmma::store_matrix_sync(Sb + (size_t)(i0 + wm + i * 16) * Tn + j0 + wn + j * 16,
                                    acc[i][j], Tn, wmma::mem_row_major);
}

// =============================================================================
// Kernel 4: warp-per-row softmax stats + in-place normalize S -> P.
// =============================================================================
__global__ __launch_bounds__(256) void stats_k() {
    const int b = blockIdx.y;
    const int wid = threadIdx.x >> 5, lane = threadIdx.x & 31;
    const int gi = blockIdx.x * 8 + wid;
    float* S = g_S + ((size_t)b * Tn + gi) * Tn;
    const int len = gi + 1;
    const int tileEnd = (gi & ~127) + 128;

    float rm = -CUDART_INF_F, rl = 0.f;
    for (int j0 = lane * 4; j0 < len; j0 += 128) {
        float4 s = *(const float4*)(S + j0);
        float v0 = (j0 + 0 < len) ? s.x : -CUDART_INF_F;
        float v1 = (j0 + 1 < len) ? s.y : -CUDART_INF_F;
        float v2 = (j0 + 2 < len) ? s.z : -CUDART_INF_F;
        float v3 = (j0 + 3 < len) ? s.w : -CUDART_INF_F;
        const float mx = fmaxf(fmaxf(v0, v1), fmaxf(v2, v3));
        if (mx > -CUDART_INF_F) {
            const float nm = fmaxf(rm, mx);
            const float keep = (rm > -CUDART_INF_F) ? rl * __expf(rm - nm) : 0.f;
            rl = keep + __expf(v0 - nm) + __expf(v1 - nm) +
                 __expf(v2 - nm) + __expf(v3 - nm);
            rm = nm;
        }
    }
#pragma unroll
    for (int o = 16; o; o >>= 1) {
        const float om = __shfl_xor_sync(0xffffffffu, rm, o);
        const float ol = __shfl_xor_sync(0xffffffffu, rl, o);
        const float nm = fmaxf(rm, om);
        const float a = (rm > -CUDART_INF_F) ? rl * __expf(rm - nm) : 0.f;
        const float c = (om > -CUDART_INF_F) ? ol * __expf(om - nm) : 0.f;
        rl = a + c;
        rm = nm;
    }
    const float inv = 1.0f / rl;

    for (int j0 = lane * 4; j0 < tileEnd; j0 += 128) {
        float4 s = *(const float4*)(S + j0);
        float4 p;
        p.x = (j0 + 0 < len) ? __expf(s.x - rm) * inv : 0.f;
        p.y = (j0 + 1 < len) ? __expf(s.y - rm) * inv : 0.f;
        p.z = (j0 + 2 < len) ? __expf(s.z - rm) * inv : 0.f;
        p.w = (j0 + 3 < len) ? __expf(s.w - rm) * inv : 0.f;
        *(float4*)(S + j0) = p;
    }
}

// =============================================================================
// Kernel 5: O = P @ V, plain tf32. Per CTA: 128 rows x 256 e-cols; warp tile
// 64x64 (acc[4][4]); double-buffered smem staging; grid e-fastest for P reuse.
// =============================================================================
constexpr int PV_PS = 128 * 36;          // one P buffer (floats)
constexpr int PV_VS = 32 * 264;          // one V buffer (floats)
constexpr int PV_SMEM = (2 * PV_PS + 2 * PV_VS) * 4;   // 104448 B

__global__ __launch_bounds__(256, 1) void pv_k(float* __restrict__ Out) {
    extern __shared__ float smem[];
    float* PsBuf[2] = { smem, smem + PV_PS };
    float* VsBuf[2] = { smem + 2 * PV_PS, smem + 2 * PV_PS + PV_VS };

    const int tid = threadIdx.x, wid = tid >> 5;
    const int b = blockIdx.z;
    const int rt = (int)gridDim.y - 1 - (int)blockIdx.y;   // heavy first
    const int i0 = rt * 128;
    const int e0 = blockIdx.x * 256;
    const int wm = (wid >> 2) * 64, wn = (wid & 3) * 64;

    const float* Pb = g_S + (size_t)b * Tn * Tn + (size_t)i0 * Tn;
    const float* Vb = g_V + (size_t)b * Tn * Dn;

    FragC acc[4][4];
#pragma unroll
    for (int i = 0; i < 4; ++i)
#pragma unroll
        for (int j = 0; j < 4; ++j) wmma::fill_fragment(acc[i][j], 0.0f);

    const int nc = (rt + 1) * 4;   // 32-wide k chunks

    // stage P chunk: 128 rows x 32 cols -> Ps[r*36 + c]
    auto stageP = [&](float* Ps, int k0) {
#pragma unroll
        for (int t = 0; t < 2; ++t) {
            const int idx = tid + t * 256, r = idx >> 2, c = (idx & 3) * 8;
            float4 p0 = *(const float4*)(Pb + (size_t)r * Tn + k0 + c);
            float4 p1 = *(const float4*)(Pb + (size_t)r * Tn + k0 + c + 4);
            float* d = Ps + r * 36 + c;
            d[0] = wmma::__float_to_tf32(p0.x);
            d[1] = wmma::__float_to_tf32(p0.y);
            d[2] = wmma::__float_to_tf32(p0.z);
            d[3] = wmma::__float_to_tf32(p0.w);
            d[4] = wmma::__float_to_tf32(p1.x);
            d[5] = wmma::__float_to_tf32(p1.y);
            d[6] = wmma::__float_to_tf32(p1.z);
            d[7] = wmma::__float_to_tf32(p1.w);
        }
    };
    // stage V chunk: 32 rows x 256 cols -> Vs[r*264 + c]
    auto stageV = [&](float* Vs, int k0) {
#pragma unroll
        for (int t = 0; t < 8; ++t) {
            const int idx = tid + t * 256, r = idx >> 6, c = (idx & 63) * 4;
            float4 v = *(const float4*)(Vb + (size_t)(k0 + r) * Dn + e0 + c);
            float* d = Vs + r * 264 + c;
            d[0] = wmma::__float_to_tf32(v.x);
            d[1] = wmma::__float_to_tf32(v.y);
            d[2] = wmma::__float_to_tf32(v.z);
            d[3] = wmma::__float_to_tf32(v.w);
        }
    };

    stageP(PsBuf[0], 0);
    stageV(VsBuf[0], 0);
    __syncthreads();

    for (int c = 0; c < nc; ++c) {
        const int cur = c & 1, nxt = cur ^ 1;
        if (c + 1 < nc) {
            stageP(PsBuf[nxt], (c + 1) * 32);
            stageV(VsBuf[nxt], (c + 1) * 32);
        }
        const float* Ps = PsBuf[cur];
        const float* Vs = VsBuf[cur];
#pragma unroll
        for (int kk = 0; kk < 4; ++kk) {
            FragA a[4];
            FragBr bb[4];
#pragma unroll
            for (int i = 0; i < 4; ++i)
                wmma::load_matrix_sync(a[i], Ps + (wm + i * 16) * 36 + kk * 8, 36);
#pragma unroll
            for (int j = 0; j < 4; ++j)
                wmma::load_matrix_sync(bb[j], Vs + (kk * 8) * 264 + wn + j * 16, 264);
#pragma unroll
            for (int i = 0; i < 4; ++i)
#pragma unroll
                for (int j = 0; j < 4; ++j)
                    wmma::mma_sync(acc[i][j], a[i], bb[j], acc[i][j]);
        }
        __syncthreads();
    }

#pragma unroll
    for (int i = 0; i < 4; ++i)
#pragma unroll
        for (int j = 0; j < 4; ++j)
            wmma::store_matrix_sync(Out + (size_t)(b * Tn + i0 + wm + i * 16) * Dn + e0 + wn + j * 16,
                                    acc[i][j], Dn, wmma::mem_row_major);
}

// =============================================================================
extern "C" void kernel_launch(void* const* d_in, const int* in_sizes, int n_in,
                              void* d_out, int out_size) {
    const float* x  = (const float*)d_in[0];
    const float* Wk = (const float*)d_in[1];
    const float* Wq = (const float*)d_in[2];
    const float* Wv = (const float*)d_in[3];
    float* out = (float*)d_out;

    const int SM_SCORES = 2 * 128 * 68 * 4;   // 69632 B
    cudaFuncSetAttribute(scores_k, cudaFuncAttributeMaxDynamicSharedMemorySize, SM_SCORES);
    cudaFuncSetAttribute(pv_k, cudaFuncAttributeMaxDynamicSharedMemorySize, PV_SMEM);

    proj_qk<<<Mt / 128, 256>>>(x, Wq, Wk);
    proj_v<<<dim3(Dn / 128, Mt / 128), 256>>>(x, Wv);

    const int npairs = (Tn / 128) * (Tn / 128 + 1) / 2;   // 528
    scores_k<<<dim3(npairs, Bn), 256, SM_SCORES>>>();

    stats_k<<<dim3(Tn / 8, Bn), 256>>>();

    // e-fastest grid: 4 consecutive CTAs share one P row-tile via L2
    pv_k<<<dim3(Dn / 256, Tn / 128, Bn), 256, PV_SMEM>>>(out);
}

// round 10
// speedup vs baseline: 1.5702x; 1.5702x over previous
#include <cuda_runtime.h>
#include <math_constants.h>
#include <mma.h>
#include <cstdint>

using namespace nvcuda;

constexpr int Bn = 4, Tn = 4096, Dn = 1024, Hn = 64;
constexpr int Mt = Bn * Tn;              // 16384 tokens
constexpr float SCALE = 0.125f;          // 1/sqrt(64)

// ----------------------------- scratch --------------------------------------
__device__ float g_Q[(size_t)Mt * Hn];           // Q (near-fp32, 3xTF32 product)
__device__ float g_K[(size_t)Mt * Hn];           // K
__device__ float g_V[(size_t)Mt * Dn];           // V, natural [token][e]
__device__ float g_S[(size_t)Bn * Tn * Tn];      // raw scores -> normalized P

// ----------------------------- wmma types -----------------------------------
using FragA  = wmma::fragment<wmma::matrix_a, 16, 16, 8, wmma::precision::tf32, wmma::row_major>;
using FragBc = wmma::fragment<wmma::matrix_b, 16, 16, 8, wmma::precision::tf32, wmma::col_major>;
using FragBr = wmma::fragment<wmma::matrix_b, 16, 16, 8, wmma::precision::tf32, wmma::row_major>;
using FragC  = wmma::fragment<wmma::accumulator, 16, 16, 8, float>;

template <class F>
__device__ __forceinline__ void split_frag(const F& x, F& hi, F& lo) {
#pragma unroll
    for (int i = 0; i < x.num_elements; ++i) {
        float h = wmma::__float_to_tf32(x.x[i]);
        hi.x[i] = h;
        lo.x[i] = wmma::__float_to_tf32(x.x[i] - h);
    }
}

// =============================================================================
// Kernel 1: fused Q+K projection, 3xTF32. C[128 x 128] = x_tile * [Wq;Wk]^T
// =============================================================================
__global__ __launch_bounds__(256) void proj_qk(const float* __restrict__ x,
                                               const float* __restrict__ Wq,
                                               const float* __restrict__ Wk) {
    __shared__ float As[128][36];
    __shared__ float Bs[128][36];
    const int tid = threadIdx.x, wid = tid >> 5;
    const int bm = blockIdx.x * 128;
    const int wm = (wid >> 2) * 64, wn = (wid & 3) * 32;

    FragC acc[4][2];
#pragma unroll
    for (int i = 0; i < 4; ++i)
#pragma unroll
        for (int j = 0; j < 2; ++j) wmma::fill_fragment(acc[i][j], 0.0f);

    for (int k0 = 0; k0 < Dn; k0 += 32) {
#pragma unroll
        for (int t = 0; t < 4; ++t) {
            const int idx = tid + t * 256, r = idx >> 3, c = (idx & 7) * 4;
            float4 v = *(const float4*)(x + (size_t)(bm + r) * Dn + k0 + c);
            As[r][c] = v.x; As[r][c + 1] = v.y; As[r][c + 2] = v.z; As[r][c + 3] = v.w;
            const float* wsrc = (r < 64) ? (Wq + (size_t)r * Dn) : (Wk + (size_t)(r - 64) * Dn);
            float4 w = *(const float4*)(wsrc + k0 + c);
            Bs[r][c] = w.x; Bs[r][c + 1] = w.y; Bs[r][c + 2] = w.z; Bs[r][c + 3] = w.w;
        }
        __syncthreads();
#pragma unroll
        for (int kk = 0; kk < 4; ++kk) {
            FragA ah[4], al[4];
            FragBc bh[2], bl[2];
#pragma unroll
            for (int i = 0; i < 4; ++i) {
                FragA a;
                wmma::load_matrix_sync(a, &As[wm + i * 16][kk * 8], 36);
                split_frag(a, ah[i], al[i]);
            }
#pragma unroll
            for (int j = 0; j < 2; ++j) {
                FragBc b;
                wmma::load_matrix_sync(b, &Bs[wn + j * 16][kk * 8], 36);
                split_frag(b, bh[j], bl[j]);
            }
#pragma unroll
            for (int i = 0; i < 4; ++i)
#pragma unroll
                for (int j = 0; j < 2; ++j) {
                    wmma::mma_sync(acc[i][j], ah[i], bh[j], acc[i][j]);
                    wmma::mma_sync(acc[i][j], ah[i], bl[j], acc[i][j]);
                    wmma::mma_sync(acc[i][j], al[i], bh[j], acc[i][j]);
                }
        }
        __syncthreads();
    }
#pragma unroll
    for (int i = 0; i < 4; ++i)
#pragma unroll
        for (int j = 0; j < 2; ++j) {
            const int row = bm + wm + i * 16;
            const int col = wn + j * 16;
            float* dst = (col < 64) ? (g_Q + (size_t)row * Hn + col)
                                    : (g_K + (size_t)row * Hn + (col - 64));
            wmma::store_matrix_sync(dst, acc[i][j], Hn, wmma::mem_row_major);
        }
}

// =============================================================================
// Kernel 2: V projection, plain tf32. Grid e-fastest: consecutive CTAs share
// the x row-tile and Wv via L2.
// =============================================================================
__global__ __launch_bounds__(256) void proj_v(const float* __restrict__ x,
                                              const float* __restrict__ Wv) {
    __shared__ float As[128][36];
    __shared__ float Bs[128][36];
    const int tid = threadIdx.x, wid = tid >> 5;
    const int e0 = blockIdx.x * 128;
    const int bm = blockIdx.y * 128;
    const int wm = (wid >> 2) * 64, wn = (wid & 3) * 32;

    FragC acc[4][2];
#pragma unroll
    for (int i = 0; i < 4; ++i)
#pragma unroll
        for (int j = 0; j < 2; ++j) wmma::fill_fragment(acc[i][j], 0.0f);

    for (int k0 = 0; k0 < Dn; k0 += 32) {
#pragma unroll
        for (int t = 0; t < 4; ++t) {
            const int idx = tid + t * 256, r = idx >> 3, c = (idx & 7) * 4;
            float4 v = *(const float4*)(x + (size_t)(bm + r) * Dn + k0 + c);
            As[r][c] = wmma::__float_to_tf32(v.x);
            As[r][c + 1] = wmma::__float_to_tf32(v.y);
            As[r][c + 2] = wmma::__float_to_tf32(v.z);
            As[r][c + 3] = wmma::__float_to_tf32(v.w);
            float4 w = *(const float4*)(Wv + (size_t)(e0 + r) * Dn + k0 + c);
            Bs[r][c] = wmma::__float_to_tf32(w.x);
            Bs[r][c + 1] = wmma::__float_to_tf32(w.y);
            Bs[r][c + 2] = wmma::__float_to_tf32(w.z);
            Bs[r][c + 3] = wmma::__float_to_tf32(w.w);
        }
        __syncthreads();
#pragma unroll
        for (int kk = 0; kk < 4; ++kk) {
            FragA a[4];
            FragBc b[2];
#pragma unroll
            for (int i = 0; i < 4; ++i)
                wmma::load_matrix_sync(a[i], &As[wm + i * 16][kk * 8], 36);
#pragma unroll
            for (int j = 0; j < 2; ++j)
                wmma::load_matrix_sync(b[j], &Bs[wn + j * 16][kk * 8], 36);
#pragma unroll
            for (int i = 0; i < 4; ++i)
#pragma unroll
                for (int j = 0; j < 2; ++j)
                    wmma::mma_sync(acc[i][j], a[i], b[j], acc[i][j]);
        }
        __syncthreads();
    }
#pragma unroll
    for (int i = 0; i < 4; ++i)
#pragma unroll
        for (int j = 0; j < 2; ++j)
            wmma::store_matrix_sync(g_V + (size_t)(bm + wm + i * 16) * Dn + e0 + wn + j * 16,
                                    acc[i][j], Dn, wmma::mem_row_major);
}

// =============================================================================
// Kernel 3: scores, 3xTF32, SCALE folded into Q. One CTA per (rt, jt<=rt, b).
// =============================================================================
__global__ __launch_bounds__(256) void scores_k() {
    extern __shared__ float dynf[];
    float (*Qs)[68] = (float(*)[68])dynf;               // 128 x 68
    float (*Ks)[68] = (float(*)[68])(dynf + 128 * 68);  // 128 x 68

    const int tid = threadIdx.x, wid = tid >> 5;
    const int b = blockIdx.y;
    int idx = blockIdx.x;
    int rt = (int)((sqrtf(8.0f * idx + 1.0f) - 1.0f) * 0.5f);
    while ((rt + 1) * (rt + 2) / 2 <= idx) ++rt;
    while (rt * (rt + 1) / 2 > idx) --rt;
    const int jt = idx - rt * (rt + 1) / 2;
    const int i0 = rt * 128, j0 = jt * 128;
    const int wm = (wid >> 2) * 64, wn = (wid & 3) * 32;

    const float* Qb = g_Q + (size_t)(b * Tn + i0) * Hn;
    const float* Kb = g_K + (size_t)(b * Tn + j0) * Hn;
    float* Sb = g_S + (size_t)b * Tn * Tn;

#pragma unroll
    for (int t = 0; t < 8; ++t) {
        const int id2 = tid + t * 256, r = id2 >> 4, c = (id2 & 15) * 4;
        float4 q = *(const float4*)(Qb + (size_t)r * Hn + c);
        Qs[r][c] = q.x * SCALE; Qs[r][c + 1] = q.y * SCALE;
        Qs[r][c + 2] = q.z * SCALE; Qs[r][c + 3] = q.w * SCALE;
        float4 k = *(const float4*)(Kb + (size_t)r * Hn + c);
        Ks[r][c] = k.x; Ks[r][c + 1] = k.y; Ks[r][c + 2] = k.z; Ks[r][c + 3] = k.w;
    }
    __syncthreads();

    FragC acc[4][2];
#pragma unroll
    for (int i = 0; i < 4; ++i)
#pragma unroll
        for (int j = 0; j < 2; ++j) wmma::fill_fragment(acc[i][j], 0.0f);

#pragma unroll
    for (int kk = 0; kk < 8; ++kk) {
        FragA ah[4], al[4];
        FragBc bh[2], bl[2];
#pragma unroll
        for (int i = 0; i < 4; ++i) {
            FragA a;
            wmma::load_matrix_sync(a, &Qs[wm + i * 16][kk * 8], 68);
            split_frag(a, ah[i], al[i]);
        }
#pragma unroll
        for (int j = 0; j < 2; ++j) {
            FragBc bb;
            wmma::load_matrix_sync(bb, &Ks[wn + j * 16][kk * 8], 68);
            split_frag(bb, bh[j], bl[j]);
        }
#pragma unroll
        for (int i = 0; i < 4; ++i)
#pragma unroll
            for (int j = 0; j < 2; ++j) {
                wmma::mma_sync(acc[i][j], ah[i], bh[j], acc[i][j]);
                wmma::mma_sync(acc[i][j], ah[i], bl[j], acc[i][j]);
                wmma::mma_sync(acc[i][j], al[i], bh[j], acc[i][j]);
            }
    }
#pragma unroll
    for (int i = 0; i < 4; ++i)
#pragma unroll
        for (int j = 0; j < 2; ++j)
            wmma::store_matrix_sync(Sb + (size_t)(i0 + wm + i * 16) * Tn + j0 + wn + j * 16,
                                    acc[i][j], Tn, wmma::mem_row_major);
}

// =============================================================================
// Kernel 4: warp-per-row softmax stats + in-place normalize S -> P.
// =============================================================================
__global__ __launch_bounds__(256) void stats_k() {
    const int b = blockIdx.y;
    const int wid = threadIdx.x >> 5, lane = threadIdx.x & 31;
    const int gi = blockIdx.x * 8 + wid;
    float* S = g_S + ((size_t)b * Tn + gi) * Tn;
    const int len = gi + 1;
    const int tileEnd = (gi & ~127) + 128;

    float rm = -CUDART_INF_F, rl = 0.f;
    for (int j0 = lane * 4; j0 < len; j0 += 128) {
        float4 s = *(const float4*)(S + j0);
        float v0 = (j0 + 0 < len) ? s.x : -CUDART_INF_F;
        float v1 = (j0 + 1 < len) ? s.y : -CUDART_INF_F;
        float v2 = (j0 + 2 < len) ? s.z : -CUDART_INF_F;
        float v3 = (j0 + 3 < len) ? s.w : -CUDART_INF_F;
        const float mx = fmaxf(fmaxf(v0, v1), fmaxf(v2, v3));
        if (mx > -CUDART_INF_F) {
            const float nm = fmaxf(rm, mx);
            const float keep = (rm > -CUDART_INF_F) ? rl * __expf(rm - nm) : 0.f;
            rl = keep + __expf(v0 - nm) + __expf(v1 - nm) +
                 __expf(v2 - nm) + __expf(v3 - nm);
            rm = nm;
        }
    }
#pragma unroll
    for (int o = 16; o; o >>= 1) {
        const float om = __shfl_xor_sync(0xffffffffu, rm, o);
        const float ol = __shfl_xor_sync(0xffffffffu, rl, o);
        const float nm = fmaxf(rm, om);
        const float a = (rm > -CUDART_INF_F) ? rl * __expf(rm - nm) : 0.f;
        const float c = (om > -CUDART_INF_F) ? ol * __expf(om - nm) : 0.f;
        rl = a + c;
        rm = nm;
    }
    const float inv = 1.0f / rl;

    for (int j0 = lane * 4; j0 < tileEnd; j0 += 128) {
        float4 s = *(const float4*)(S + j0);
        float4 p;
        p.x = (j0 + 0 < len) ? __expf(s.x - rm) * inv : 0.f;
        p.y = (j0 + 1 < len) ? __expf(s.y - rm) * inv : 0.f;
        p.z = (j0 + 2 < len) ? __expf(s.z - rm) * inv : 0.f;
        p.w = (j0 + 3 < len) ? __expf(s.w - rm) * inv : 0.f;
        *(float4*)(S + j0) = p;
    }
}

// =============================================================================
// Kernel 5: O = P @ V, plain tf32, smem-staged, k-chunk 32, occupancy 2.
// Grid e-fastest: 8 consecutive CTAs share one P row-tile via L2; rt on y
// heavy-first. (Body identical to the 1935us version.)
// =============================================================================
__global__ __launch_bounds__(256, 2) void pv_k(float* __restrict__ Out) {
    __shared__ float Ps[128][36];   // [m][k]
    __shared__ float Vs[32][132];   // [k][n]
    const int tid = threadIdx.x, wid = tid >> 5;
    const int b = blockIdx.z;
    const int rt = (int)gridDim.y - 1 - (int)blockIdx.y;   // heavy first
    const int i0 = rt * 128;
    const int e0 = blockIdx.x * 128;
    const int wm = (wid >> 2) * 64, wn = (wid & 3) * 32;

    const float* Pb = g_S + (size_t)b * Tn * Tn + (size_t)i0 * Tn;
    const float* Vb = g_V + (size_t)b * Tn * Dn;

    FragC acc[4][2];
#pragma unroll
    for (int i = 0; i < 4; ++i)
#pragma unroll
        for (int j = 0; j < 2; ++j) wmma::fill_fragment(acc[i][j], 0.0f);

    const int kEnd = (rt + 1) * 128;
    for (int k0 = 0; k0 < kEnd; k0 += 32) {
        // stage P 128x32 (pre-rounded to tf32)
#pragma unroll
        for (int t = 0; t < 2; ++t) {
            const int idx = tid + t * 256, r = idx >> 2, c = (idx & 3) * 8;
            float4 p0 = *(const float4*)(Pb + (size_t)r * Tn + k0 + c);
            float4 p1 = *(const float4*)(Pb + (size_t)r * Tn + k0 + c + 4);
            Ps[r][c + 0] = wmma::__float_to_tf32(p0.x);
            Ps[r][c + 1] = wmma::__float_to_tf32(p0.y);
            Ps[r][c + 2] = wmma::__float_to_tf32(p0.z);
            Ps[r][c + 3] = wmma::__float_to_tf32(p0.w);
            Ps[r][c + 4] = wmma::__float_to_tf32(p1.x);
            Ps[r][c + 5] = wmma::__float_to_tf32(p1.y);
            Ps[r][c + 6] = wmma::__float_to_tf32(p1.z);
            Ps[r][c + 7] = wmma::__float_to_tf32(p1.w);
        }
        // stage V 32x128 (pre-rounded to tf32)
#pragma unroll
        for (int t = 0; t < 4; ++t) {
            const int idx = tid + t * 256, r = idx >> 5, c = (idx & 31) * 4;
            float4 v = *(const float4*)(Vb + (size_t)(k0 + r) * Dn + e0 + c);
            Vs[r][c + 0] = wmma::__float_to_tf32(v.x);
            Vs[r][c + 1] = wmma::__float_to_tf32(v.y);
            Vs[r][c + 2] = wmma::__float_to_tf32(v.z);
            Vs[r][c + 3] = wmma::__float_to_tf32(v.w);
        }
        __syncthreads();
#pragma unroll
        for (int kk = 0; kk < 4; ++kk) {
            FragA a[4];
            FragBr bfr[2];
#pragma unroll
            for (int i = 0; i < 4; ++i)
                wmma::load_matrix_sync(a[i], &Ps[wm + i * 16][kk * 8], 36);
#pragma unroll
            for (int j = 0; j < 2; ++j)
                wmma::load_matrix_sync(bfr[j], &Vs[kk * 8][wn + j * 16], 132);
#pragma unroll
            for (int i = 0; i < 4; ++i)
#pragma unroll
                for (int j = 0; j < 2; ++j)
                    wmma::mma_sync(acc[i][j], a[i], bfr[j], acc[i][j]);
        }
        __syncthreads();
    }
#pragma unroll
    for (int i = 0; i < 4; ++i)
#pragma unroll
        for (int j = 0; j < 2; ++j)
            wmma::store_matrix_sync(Out + (size_t)(b * Tn + i0 + wm + i * 16) * Dn + e0 + wn + j * 16,
                                    acc[i][j], Dn, wmma::mem_row_major);
}

// =============================================================================
extern "C" void kernel_launch(void* const* d_in, const int* in_sizes, int n_in,
                              void* d_out, int out_size) {
    const float* x  = (const float*)d_in[0];
    const float* Wk = (const float*)d_in[1];
    const float* Wq = (const float*)d_in[2];
    const float* Wv = (const float*)d_in[3];
    float* out = (float*)d_out;

    const int SM_SCORES = 2 * 128 * 68 * 4;   // 69632 B
    cudaFuncSetAttribute(scores_k, cudaFuncAttributeMaxDynamicSharedMemorySize, SM_SCORES);

    proj_qk<<<Mt / 128, 256>>>(x, Wq, Wk);
    proj_v<<<dim3(Dn / 128, Mt / 128), 256>>>(x, Wv);

    const int npairs = (Tn / 128) * (Tn / 128 + 1) / 2;   // 528
    scores_k<<<dim3(npairs, Bn), 256, SM_SCORES>>>();

    stats_k<<<dim3(Tn / 8, Bn), 256>>>();

    // e-fastest grid: 8 consecutive CTAs share one P row-tile via L2
    pv_k<<<dim3(Dn / 128, Tn / 128, Bn), 256>>>(out);
}